// round 12
// baseline (speedup 1.0000x reference)
#include <cuda_runtime.h>
#include <cuda_fp16.h>
#include <math.h>

// Problem dims
#define NB 64      // batch
#define NT 512     // timesteps
#define ND 256     // input dim
#define NH 1024    // hidden
#define NL 256     // latent
#define NO 256     // output
#define NG 4096    // 4*NH gates
#define KR 1280    // NL + NH
#define BTO (NB*NT*NO)
#define NCTAS 144

// f16 SMEM layout (units = __half)
#define SWG_STRIDE 1288                    // gate weights: 32 x (1280+8)
#define SWE_STRIDE 1032                    // enc weights: 16 x (1024+8)
#define SWH_STRIDE 264                     // head weights: 32 x (256+8)
#define SA_STRIDE 264                      // A tiles: 64 x (256+8)
#define GATE_SA0 (32*SWG_STRIDE)           // 41216
#define GATE_SA1 (GATE_SA0 + 64*SA_STRIDE)
#define GATE_HALFS (GATE_SA1 + 64*SA_STRIDE)   // 75008
#define EH_HEAD_OFF (16*SWE_STRIDE)
#define EH_SA0 (EH_HEAD_OFF + 32*SWH_STRIDE)
#define EH_SA1 (EH_SA0 + 64*SA_STRIDE)
#define SMEM_BYTES (GATE_HALFS*2)          // 150016

// ---------------- device globals ---------------------------------------------
__device__ __align__(16) float g_Xp[NT * NB * NG];  // x-proj + biases [t][b][j]
__device__ __align__(16) float g_Wg[NG * KR];       // fallback packed gate weights
__device__ __align__(16) __half g_h[NB * NH];       // h state (f16)
__device__ __align__(16) __half g_s[NB * NL];       // s state (f16)
__device__ __align__(16) float g_hs[2][NB * KR];    // fallback state
__device__ __align__(16) float g_c[NB * NH];
__device__ unsigned g_arr[NCTAS * 8];               // per-CTA arrival flags (32B apart)
__device__ unsigned g_rel;                          // release epoch

// ---------------- helpers ----------------------------------------------------
__device__ __forceinline__ float to_tf32(float x) {
    unsigned u;
    asm("cvt.rna.tf32.f32 %0, %1;" : "=r"(u) : "f"(x));
    return __uint_as_float(u);
}
__device__ __forceinline__ float sigmoidf_(float x) { return 1.0f / (1.0f + expf(-x)); }

__device__ __forceinline__ unsigned smem_u32(const void* p) {
    return (unsigned)__cvta_generic_to_shared(p);
}
__device__ __forceinline__ void ldm_x4(unsigned a[4], unsigned addr) {
    asm volatile("ldmatrix.sync.aligned.m8n8.x4.shared.b16 {%0,%1,%2,%3}, [%4];"
                 : "=r"(a[0]), "=r"(a[1]), "=r"(a[2]), "=r"(a[3]) : "r"(addr));
}
__device__ __forceinline__ void ldm_x2(unsigned b[2], unsigned addr) {
    asm volatile("ldmatrix.sync.aligned.m8n8.x2.shared.b16 {%0,%1}, [%2];"
                 : "=r"(b[0]), "=r"(b[1]) : "r"(addr));
}
__device__ __forceinline__ void mma16(float c[4], const unsigned a[4], const unsigned b[2]) {
    asm volatile(
        "mma.sync.aligned.m16n8k16.row.col.f32.f16.f16.f32 "
        "{%0,%1,%2,%3}, {%4,%5,%6,%7}, {%8,%9}, {%0,%1,%2,%3};"
        : "+f"(c[0]), "+f"(c[1]), "+f"(c[2]), "+f"(c[3])
        : "r"(a[0]), "r"(a[1]), "r"(a[2]), "r"(a[3]), "r"(b[0]), "r"(b[1]));
}
// fp32 tf32 mma (xproj + fallback)
__device__ __forceinline__ void mma8(float c[4], const unsigned a[4],
                                     unsigned b0, unsigned b1) {
    asm volatile(
        "mma.sync.aligned.m16n8k8.row.col.f32.tf32.tf32.f32 "
        "{%0,%1,%2,%3}, {%4,%5,%6,%7}, {%8,%9}, {%0,%1,%2,%3};\n"
        : "+f"(c[0]), "+f"(c[1]), "+f"(c[2]), "+f"(c[3])
        : "r"(a[0]), "r"(a[1]), "r"(a[2]), "r"(a[3]), "r"(b0), "r"(b1));
}

// ldmatrix address helpers (strides in __half units; layouts row-major)
__device__ __forceinline__ unsigned a_addr(const __half* sA, int m_base, int kof, int lane) {
    int grp = lane >> 3, rin = lane & 7;
    return smem_u32(sA + (m_base + (grp & 1) * 8 + rin) * SA_STRIDE + kof + (grp >> 1) * 8);
}
__device__ __forceinline__ unsigned b_addr(const __half* sW, int stride, int j0, int kof, int lane) {
    int lm = lane & 15;
    return smem_u32(sW + (j0 + (lm & 7)) * stride + kof + ((lm >> 3) & 1) * 8);
}

// stage a 64 x 256 f16 chunk: global (row stride lds) -> regs -> smem (stride 264)
__device__ __forceinline__ void lda256(uint4 rv[8], const __half* gsrc, int lds, int kc, int tid) {
    int row = tid >> 2, q = tid & 3;
    const uint4* s = reinterpret_cast<const uint4*>(gsrc + (size_t)row * lds + kc + q * 64);
#pragma unroll
    for (int i = 0; i < 8; i++) rv[i] = s[i];
}
__device__ __forceinline__ void sta256(const uint4 rv[8], __half* sA, int tid) {
    int row = tid >> 2, q = tid & 3;
    uint4* d = reinterpret_cast<uint4*>(sA + row * SA_STRIDE + q * 64);
#pragma unroll
    for (int i = 0; i < 8; i++) d[i] = rv[i];
}

// fp32 staging (xproj + fallback)
__device__ __forceinline__ void stage_A_fb(float* sA, const float* A0, int strideA,
                                           int kc, int tid) {
    int rbase = tid >> 4, c4 = (tid & 15) * 4;
#pragma unroll
    for (int i = 0; i < 4; i++) {
        const float4 v = *reinterpret_cast<const float4*>(A0 + (size_t)(rbase + i * 16) * strideA + kc + c4);
        float* d = sA + (rbase + i * 16) * 68 + c4;
        d[0] = to_tf32(v.x); d[1] = to_tf32(v.y);
        d[2] = to_tf32(v.z); d[3] = to_tf32(v.w);
    }
}
__device__ __forceinline__ void load_afrag_fb(unsigned a[4], const float* sA,
                                              int rowbase, int r, int cc, int k8) {
    const float* s0 = sA + (rowbase + r) * 68 + k8 * 8;
    a[0] = __float_as_uint(s0[cc]);
    a[1] = __float_as_uint(s0[8 * 68 + cc]);
    a[2] = __float_as_uint(s0[cc + 4]);
    a[3] = __float_as_uint(s0[8 * 68 + cc + 4]);
}

// distributed-flag grid barrier (single co-resident wave), WATCHDOG-protected:
// arrival = private flag store; sweep = CTA0 threads poll all flags in parallel;
// release = one broadcast line. Any sync failure escapes after ~100 ms and the
// bench reports wrong numerics instead of hanging the container.
__device__ __forceinline__ void grid_bar(unsigned ep, int bx, int tid) {
    __syncthreads();
    if (tid == 0) {
        __threadfence();
        *(volatile unsigned*)&g_arr[bx * 8] = ep;
    }
    if (bx == 0) {
        if (tid < NCTAS) {
            long long start = clock64();
            while (*(volatile unsigned*)&g_arr[tid * 8] < ep) {
                if (clock64() - start > 200000000LL) break;   // watchdog
            }
        }
        __syncthreads();
        if (tid == 0) {
            __threadfence();
            *(volatile unsigned*)&g_rel = ep;
        }
    }
    if (tid == 0) {
        long long start = clock64();
        while (*(volatile unsigned*)&g_rel < ep) {
            if (clock64() - start > 200000000LL) break;       // watchdog
        }
        __threadfence();
    }
    __syncthreads();
}

__global__ void init_kernel() {
    for (int i = threadIdx.x; i < NCTAS * 8; i += blockDim.x) g_arr[i] = 0;
    if (threadIdx.x == 0) g_rel = 0;
}

// ---------------- xproj (unchanged, proven) ----------------------------------
__global__ void __launch_bounds__(256) xproj_kernel(const float* __restrict__ x,
                                                    const float* __restrict__ W_ih,
                                                    const float* __restrict__ b_ih,
                                                    const float* __restrict__ b_hh) {
    __shared__ float smem[64 * 68];
    int t = blockIdx.x;
    int n0 = blockIdx.y * 64;
    int tid = threadIdx.x;
    int lane = tid & 31, w = tid >> 5;
    int wm = w & 1, wn = w >> 1, r = lane >> 2, cc = lane & 3;
    float C[2][2][4] = {};
    const float* A0 = x + t * ND;
    for (int kc = 0; kc < ND; kc += 64) {
        stage_A_fb(smem, A0, NT * ND, kc, tid);
        __syncthreads();
#pragma unroll
        for (int k8 = 0; k8 < 8; k8++) {
            unsigned a0[4], a1[4];
            load_afrag_fb(a0, smem, wm * 32, r, cc, k8);
            load_afrag_fb(a1, smem, wm * 32 + 16, r, cc, k8);
#pragma unroll
            for (int nt = 0; nt < 2; nt++) {
                int j = n0 + wn * 16 + nt * 8 + r;
                const float* bp = W_ih + (size_t)j * (ND + NL) + kc + k8 * 8 + cc;
                unsigned b0 = __float_as_uint(to_tf32(bp[0]));
                unsigned b1 = __float_as_uint(to_tf32(bp[4]));
                mma8(C[0][nt], a0, b0, b1);
                mma8(C[1][nt], a1, b0, b1);
            }
        }
        __syncthreads();
    }
#pragma unroll
    for (int mt = 0; mt < 2; mt++)
#pragma unroll
        for (int nt = 0; nt < 2; nt++) {
            int col = n0 + wn * 16 + nt * 8 + 2 * cc;
            int row0 = wm * 32 + mt * 16 + r;
            float bs0 = b_ih[col] + b_hh[col];
            float bs1 = b_ih[col + 1] + b_hh[col + 1];
            size_t base0 = ((size_t)t * NB + row0) * NG;
            size_t base1 = ((size_t)t * NB + row0 + 8) * NG;
            g_Xp[base0 + col]     = C[mt][nt][0] + bs0;
            g_Xp[base0 + col + 1] = C[mt][nt][1] + bs1;
            g_Xp[base1 + col]     = C[mt][nt][2] + bs0;
            g_Xp[base1 + col + 1] = C[mt][nt][3] + bs1;
        }
}

// ---------------- persistent kernel (fp16 + ldmatrix) ------------------------
extern __shared__ __half dsmh[];

__global__ void __launch_bounds__(256, 1)
persist_kernel(const float* __restrict__ W_ih, const float* __restrict__ W_hh,
               const float* __restrict__ W_enc, const float* __restrict__ b_enc,
               const float* __restrict__ W_pred, const float* __restrict__ b_pred,
               const float* __restrict__ W_act, const float* __restrict__ b_act,
               float* __restrict__ out) {
    int bx = blockIdx.x;
    int tid = threadIdx.x;
    int lane = tid & 31, w = tid >> 5;
    int r = lane >> 2, cc = lane & 3;
    unsigned ep = 1;

    if (bx < 128) {
        // ================= gate CTA: 8 units x 4 gates =================
        __half* sW = dsmh;
        __half* sA0 = dsmh + GATE_SA0;
        __half* sA1 = dsmh + GATE_SA1;
        int wm = w & 1, wn = w >> 1;     // wm: m-half, wn: gate
        int u0 = bx * 8;

        for (int idx = tid; idx < 32 * KR; idx += 256) {
            int rl = idx / KR, k = idx - rl * KR;
            int g = rl >> 3, up = rl & 7;
            int j = g * NH + u0 + up;
            float v = (k < NL) ? W_ih[(size_t)j * (ND + NL) + ND + k]
                               : W_hh[(size_t)j * NH + k - NL];
            sW[rl * SWG_STRIDE + k] = __float2half(v);
        }
        for (int idx = tid; idx < 512; idx += 256) {
            int b = idx >> 3, up = idx & 7;
            g_c[b * NH + u0 + up] = 0.0f;
        }
        grid_bar(ep++, bx, tid);

        float C[2][4] = {};
        float xp[2][4];
#pragma unroll
        for (int q = 0; q < 2; q++) {            // prefetch Xp for t=0
            int idx = tid + q * 256;
            int b = idx >> 3, up = idx & 7;
            size_t base = (size_t)b * NG + u0 + up;
#pragma unroll
            for (int g = 0; g < 4; g++) xp[q][g] = __ldg(&g_Xp[base + g * NH]);
        }

        for (int t = 0; t <= NT; t++) {
            // ---------- phase A: Gs(K=256) + cell ----------
            if (t < NT) {
                uint4 rv[8];
                lda256(rv, g_s, NL, 0, tid);
                sta256(rv, sA0, tid);
                __syncthreads();
#pragma unroll 4
                for (int kk = 0; kk < 16; kk++) {
                    unsigned a0[4], a1[4], b[2];
                    ldm_x4(a0, a_addr(sA0, wm * 32, kk * 16, lane));
                    ldm_x4(a1, a_addr(sA0, wm * 32 + 16, kk * 16, lane));
                    ldm_x2(b, b_addr(sW, SWG_STRIDE, wn * 8, kk * 16, lane));
                    mma16(C[0], a0, b);
                    mma16(C[1], a1, b);
                }
                // scatter gates into sG (= sA1 region, as f32)
                float* sG = reinterpret_cast<float*>(sA1);
#pragma unroll
                for (int mt = 0; mt < 2; mt++) {
                    int brow = wm * 32 + mt * 16 + r;
                    sG[(wn * 64 + brow) * 9 + 2 * cc]         = C[mt][0];
                    sG[(wn * 64 + brow) * 9 + 2 * cc + 1]     = C[mt][1];
                    sG[(wn * 64 + brow + 8) * 9 + 2 * cc]     = C[mt][2];
                    sG[(wn * 64 + brow + 8) * 9 + 2 * cc + 1] = C[mt][3];
                }
                __syncthreads();
#pragma unroll
                for (int q = 0; q < 2; q++) {
                    int idx = tid + q * 256;
                    int b = idx >> 3, up = idx & 7, u = u0 + up;
                    float gi = sG[(0 * 64 + b) * 9 + up] + xp[q][0];
                    float gf = sG[(1 * 64 + b) * 9 + up] + xp[q][1];
                    float gg = sG[(2 * 64 + b) * 9 + up] + xp[q][2];
                    float go = sG[(3 * 64 + b) * 9 + up] + xp[q][3];
                    float ii = sigmoidf_(gi), ff = sigmoidf_(gf);
                    float gt = tanhf(gg), oo = sigmoidf_(go);
                    float cn = ff * g_c[b * NH + u] + ii * gt;
                    g_c[b * NH + u] = cn;
                    g_h[b * NH + u] = __float2half(oo * tanhf(cn));
                }
                C[0][0] = C[0][1] = C[0][2] = C[0][3] = 0.0f;
                C[1][0] = C[1][1] = C[1][2] = C[1][3] = 0.0f;
            }
            if (t == NT) break;
            grid_bar(ep++, bx, tid);

            // ---------- phase B: Gh(K=1024) for step t+1 ----------
            if (t + 1 < NT) {
#pragma unroll
                for (int q = 0; q < 2; q++) {     // prefetch Xp for t+1
                    int idx = tid + q * 256;
                    int b = idx >> 3, up = idx & 7;
                    size_t base = ((size_t)(t + 1) * NB + b) * NG + u0 + up;
#pragma unroll
                    for (int g = 0; g < 4; g++) xp[q][g] = __ldg(&g_Xp[base + g * NH]);
                }
                uint4 rv[8];
                lda256(rv, g_h, NH, 0, tid);
                sta256(rv, sA0, tid);
                lda256(rv, g_h, NH, 256, tid);
                __syncthreads();
#pragma unroll 1
                for (int c = 0; c < 4; c++) {
                    const __half* cur = (c & 1) ? sA1 : sA0;
                    int wk = NL + c * 256;
#pragma unroll 4
                    for (int kk = 0; kk < 16; kk++) {
                        unsigned a0[4], a1[4], b[2];
                        ldm_x4(a0, a_addr(cur, wm * 32, kk * 16, lane));
                        ldm_x4(a1, a_addr(cur, wm * 32 + 16, kk * 16, lane));
                        ldm_x2(b, b_addr(sW, SWG_STRIDE, wn * 8, wk + kk * 16, lane));
                        mma16(C[0], a0, b);
                        mma16(C[1], a1, b);
                    }
                    if (c + 1 < 4) {
                        sta256(rv, (c & 1) ? sA0 : sA1, tid);
                        if (c + 2 < 4) lda256(rv, g_h, NH, (c + 2) * 256, tid);
                    }
                    __syncthreads();
                }
            }
            grid_bar(ep++, bx, tid);
        }
    } else {
        // ================= enc + head CTA =================
        int e = bx - 128;
        __half* sWe = dsmh;
        __half* sWh = dsmh + EH_HEAD_OFF;
        __half* sA0 = dsmh + EH_SA0;
        __half* sA1 = dsmh + EH_SA1;

        for (int idx = tid; idx < 16 * NH; idx += 256) {
            int rl = idx >> 10, k = idx & 1023;
            sWe[rl * SWE_STRIDE + k] = __float2half(W_enc[(size_t)(e * 16 + rl) * NH + k]);
        }
        const float* Wh = (e < 8) ? W_act : W_pred;
        int hr0 = (e < 8) ? e * 32 : (e - 8) * 32;
        for (int idx = tid; idx < 32 * NL; idx += 256) {
            int rl = idx >> 8, k = idx & 255;
            sWh[rl * SWH_STRIDE + k] = __float2half(Wh[(size_t)(hr0 + rl) * NL + k]);
        }
        for (int idx = tid; idx < 1024; idx += 256) {
            int b = idx >> 4, q = idx & 15;
            g_s[b * NL + e * 16 + q] = __float2half(0.0f);
        }
        grid_bar(ep++, bx, tid);

        for (int t = 0; t <= NT; t++) {
            // ---------- phase A: heads for step t-1 (K=256 from g_s) ----------
            if (t >= 1) {
                int wm = w & 1, wn = w >> 1;
                float C[2][4] = {};
                uint4 rv[8];
                lda256(rv, g_s, NL, 0, tid);
                sta256(rv, sA0, tid);
                __syncthreads();
#pragma unroll 4
                for (int kk = 0; kk < 16; kk++) {
                    unsigned a0[4], a1[4], b[2];
                    ldm_x4(a0, a_addr(sA0, wm * 32, kk * 16, lane));
                    ldm_x4(a1, a_addr(sA0, wm * 32 + 16, kk * 16, lane));
                    ldm_x2(b, b_addr(sWh, SWH_STRIDE, wn * 8, kk * 16, lane));
                    mma16(C[0], a0, b);
                    mma16(C[1], a1, b);
                }
                bool isAct = (e < 8);
                const float* bias = isAct ? b_act : b_pred;
                size_t obase = isAct ? (size_t)0 : (size_t)2 * BTO;
#pragma unroll
                for (int mt = 0; mt < 2; mt++) {
                    int row0 = wm * 32 + mt * 16 + r;
                    int coll = hr0 + wn * 8 + 2 * cc;
#pragma unroll
                    for (int el = 0; el < 4; el++) {
                        int rr = row0 + (el >> 1) * 8;
                        int col = coll + (el & 1);
                        float v = C[mt][el] + __ldg(&bias[col]);
                        if (!isAct) v = tanhf(v);
                        out[obase + ((size_t)rr * NT + (t - 1)) * NO + col] = v;
                    }
                }
            }
            if (t == NT) break;
            grid_bar(ep++, bx, tid);

            // ---------- phase B: enc 16 cols (K=1024 from g_h) ----------
            {
                int wm4 = w & 3, wn2 = w >> 2;
                float C[4] = {};
                uint4 rv[8];
                lda256(rv, g_h, NH, 0, tid);
                sta256(rv, sA0, tid);
                lda256(rv, g_h, NH, 256, tid);
                __syncthreads();
#pragma unroll 1
                for (int c = 0; c < 4; c++) {
                    const __half* cur = (c & 1) ? sA1 : sA0;
#pragma unroll 4
                    for (int kk = 0; kk < 16; kk++) {
                        unsigned a0[4], b[2];
                        ldm_x4(a0, a_addr(cur, wm4 * 16, kk * 16, lane));
                        ldm_x2(b, b_addr(sWe, SWE_STRIDE, wn2 * 8, c * 256 + kk * 16, lane));
                        mma16(C, a0, b);
                    }
                    if (c + 1 < 4) {
                        sta256(rv, (c & 1) ? sA0 : sA1, tid);
                        if (c + 2 < 4) lda256(rv, g_h, NH, (c + 2) * 256, tid);
                    }
                    __syncthreads();
                }
                int row0 = wm4 * 16 + r;
                int coll = e * 16 + wn2 * 8 + 2 * cc;
#pragma unroll
                for (int el = 0; el < 4; el++) {
                    int rr = row0 + (el >> 1) * 8;
                    int col = coll + (el & 1);
                    float v = tanhf(C[el] + __ldg(&b_enc[col]));
                    g_s[rr * NL + col] = __float2half(v);
                    out[(size_t)BTO + ((size_t)rr * NT + t) * NL + col] = v;
                }
            }
            grid_bar(ep++, bx, tid);
        }
    }
}

// ================= fallback path (proven in R6/R8; terminates always) ========
__global__ void __launch_bounds__(256) prep_fb_kernel(const float* __restrict__ W_ih,
                                                      const float* __restrict__ W_hh) {
    const int N0 = NG * KR;
    const int N1 = 2 * NB * KR;
    const int N2 = NB * NH;
    const int total = N0 + N1 + N2;
    for (int i = blockIdx.x * blockDim.x + threadIdx.x; i < total;
         i += gridDim.x * blockDim.x) {
        int k = i;
        if (k < N0) {
            int j = k / KR, q = k - j * KR;
            float v = (q < NL) ? W_ih[(size_t)j * (ND + NL) + ND + q]
                               : W_hh[(size_t)j * NH + (q - NL)];
            g_Wg[k] = to_tf32(v);
        } else if ((k -= N0) < N1) {
            (&g_hs[0][0])[k] = 0.0f;
        } else {
            k -= N1;
            g_c[k] = 0.0f;
        }
    }
}

__device__ __forceinline__ void gemm_fb(float C[2][2][4], const float* A0, int strideA,
                                        const float* Bw, int ldb, int jbase, int K,
                                        float* sA) {
    int tid = threadIdx.x;
    int lane = tid & 31, w = tid >> 5;
    int wm = w & 1, wn = w >> 1, r = lane >> 2, cc = lane & 3;
    for (int kc = 0; kc < K; kc += 64) {
        stage_A_fb(sA, A0, strideA, kc, tid);
        __syncthreads();
#pragma unroll
        for (int k8 = 0; k8 < 8; k8++) {
            unsigned a0[4], a1[4];
            load_afrag_fb(a0, sA, wm * 32, r, cc, k8);
            load_afrag_fb(a1, sA, wm * 32 + 16, r, cc, k8);
#pragma unroll
            for (int nt = 0; nt < 2; nt++) {
                int j = jbase + wn * 16 + nt * 8 + r;
                const float* bp = Bw + (size_t)j * ldb + kc + k8 * 8 + cc;
                unsigned b0 = __float_as_uint(bp[0]);
                unsigned b1 = __float_as_uint(bp[4]);
                mma8(C[0][nt], a0, b0, b1);
                mma8(C[1][nt], a1, b0, b1);
            }
        }
        __syncthreads();
    }
}

__global__ void __launch_bounds__(256) step_fb_kernel(int t,
                                                      const float* __restrict__ W_pred,
                                                      const float* __restrict__ b_pred,
                                                      const float* __restrict__ W_act,
                                                      const float* __restrict__ b_act,
                                                      float* __restrict__ out) {
    __shared__ float smem[64 * 68];
    const float* hs_cur = g_hs[t & 1];
    float* hs_nxt = g_hs[(t + 1) & 1];
    int bx = blockIdx.x;
    int tid = threadIdx.x;
    int lane = tid & 31, w = tid >> 5;
    int wm = w & 1, wn = w >> 1, r = lane >> 2, cc = lane & 3;

    if (bx < 128) {
        if (t >= NT) return;
        int u0 = bx * 8;
        float C[2][4] = {};
        for (int kc = 0; kc < KR; kc += 64) {
            stage_A_fb(smem, hs_cur, KR, kc, tid);
            __syncthreads();
#pragma unroll
            for (int k8 = 0; k8 < 8; k8++) {
                unsigned a0[4], a1[4];
                load_afrag_fb(a0, smem, wm * 32, r, cc, k8);
                load_afrag_fb(a1, smem, wm * 32 + 16, r, cc, k8);
                int j = wn * NH + u0 + r;
                const float* bp = g_Wg + (size_t)j * KR + kc + k8 * 8 + cc;
                unsigned b0 = __float_as_uint(bp[0]);
                unsigned b1 = __float_as_uint(bp[4]);
                mma8(C[0], a0, b0, b1);
                mma8(C[1], a1, b0, b1);
            }
            __syncthreads();
        }
        float* sG = smem;
#pragma unroll
        for (int mt = 0; mt < 2; mt++) {
            int b0r = wm * 32 + mt * 16 + r;
            sG[(wn * 64 + b0r) * 9 + 2 * cc]         = C[mt][0];
            sG[(wn * 64 + b0r) * 9 + 2 * cc + 1]     = C[mt][1];
            sG[(wn * 64 + b0r + 8) * 9 + 2 * cc]     = C[mt][2];
            sG[(wn * 64 + b0r + 8) * 9 + 2 * cc + 1] = C[mt][3];
        }
        __syncthreads();
        for (int idx = tid; idx < 512; idx += 256) {
            int b = idx >> 3, up = idx & 7, u = u0 + up;
            size_t xb = ((size_t)t * NB + b) * NG;
            float gi = sG[(0 * 64 + b) * 9 + up] + g_Xp[xb + u];
            float gf = sG[(1 * 64 + b) * 9 + up] + g_Xp[xb + NH + u];
            float gg = sG[(2 * 64 + b) * 9 + up] + g_Xp[xb + 2 * NH + u];
            float go = sG[(3 * 64 + b) * 9 + up] + g_Xp[xb + 3 * NH + u];
            float ii = sigmoidf_(gi), ff = sigmoidf_(gf);
            float gt = tanhf(gg), oo = sigmoidf_(go);
            float cn = ff * g_c[b * NH + u] + ii * gt;
            g_c[b * NH + u] = cn;
            hs_nxt[b * KR + NL + u] = oo * tanhf(cn);
        }
    } else {
        if (t == 0) return;
        int ab = bx - 128;
        bool isAct = ab < 4;
        int n0 = (ab & 3) * 64;
        float C[2][2][4] = {};
        gemm_fb(C, hs_cur, KR, isAct ? W_act : W_pred, NL, n0, NL, smem);
        const float* bias = isAct ? b_act : b_pred;
        size_t obase = isAct ? (size_t)0 : (size_t)2 * BTO;
#pragma unroll
        for (int mt = 0; mt < 2; mt++)
#pragma unroll
            for (int nt = 0; nt < 2; nt++) {
                int col = n0 + wn * 16 + nt * 8 + 2 * cc;
                int row0 = wm * 32 + mt * 16 + r;
#pragma unroll
                for (int el = 0; el < 4; el++) {
                    int rr = row0 + (el >> 1) * 8;
                    int jj = col + (el & 1);
                    float v = C[mt][nt][el] + bias[jj];
                    if (!isAct) v = tanhf(v);
                    out[obase + ((size_t)rr * NT + (t - 1)) * NO + jj] = v;
                }
            }
    }
}

__global__ void __launch_bounds__(256) enc_fb_kernel(int t,
                                                     const float* __restrict__ W_enc,
                                                     const float* __restrict__ b_enc,
                                                     float* __restrict__ out) {
    __shared__ float smem[64 * 68];
    float* hs_nxt = g_hs[(t + 1) & 1];
    int n0 = blockIdx.x * 64;
    float C[2][2][4] = {};
    gemm_fb(C, hs_nxt + NL, KR, W_enc, NH, n0, NH, smem);

    int lane = threadIdx.x & 31, w = threadIdx.x >> 5;
    int wm = w & 1, wn = w >> 1, r = lane >> 2, cc = lane & 3;
#pragma unroll
    for (int mt = 0; mt < 2; mt++)
#pragma unroll
        for (int nt = 0; nt < 2; nt++) {
            int col = n0 + wn * 16 + nt * 8 + 2 * cc;
            int row0 = wm * 32 + mt * 16 + r;
#pragma unroll
            for (int el = 0; el < 4; el++) {
                int rr = row0 + (el >> 1) * 8;
                int jj = col + (el & 1);
                float v = tanhf(C[mt][nt][el] + b_enc[jj]);
                out[(size_t)BTO + ((size_t)rr * NT + t) * NL + jj] = v;
                hs_nxt[rr * KR + jj] = v;
            }
        }
}

// ---------------- host driver ------------------------------------------------
extern "C" void kernel_launch(void* const* d_in, const int* in_sizes, int n_in,
                              void* d_out, int out_size) {
    const float* x      = (const float*)d_in[0];
    const float* W_ih   = (const float*)d_in[1];
    const float* W_hh   = (const float*)d_in[2];
    const float* b_ih   = (const float*)d_in[3];
    const float* b_hh   = (const float*)d_in[4];
    const float* W_enc  = (const float*)d_in[5];
    const float* b_enc  = (const float*)d_in[6];
    const float* W_pred = (const float*)d_in[7];
    const float* b_pred = (const float*)d_in[8];
    const float* W_act  = (const float*)d_in[9];
    const float* b_act  = (const float*)d_in[10];
    float* out = (float*)d_out;

    int dev = 0, nsm = 0;
    cudaGetDevice(&dev);
    cudaDeviceGetAttribute(&nsm, cudaDevAttrMultiProcessorCount, dev);
    bool persistent_ok = (nsm >= NCTAS);
    if (persistent_ok) {
        cudaError_t e = cudaFuncSetAttribute(
            persist_kernel, cudaFuncAttributeMaxDynamicSharedMemorySize, SMEM_BYTES);
        if (e != cudaSuccess) { (void)cudaGetLastError(); persistent_ok = false; }
    }

    xproj_kernel<<<dim3(NT, NG / 64), 256>>>(x, W_ih, b_ih, b_hh);

    if (persistent_ok) {
        init_kernel<<<1, 256>>>();
        persist_kernel<<<NCTAS, 256, SMEM_BYTES>>>(W_ih, W_hh, W_enc, b_enc,
                                                   W_pred, b_pred, W_act, b_act, out);
    } else {
        prep_fb_kernel<<<1024, 256>>>(W_ih, W_hh);
        for (int t = 0; t < NT; t++) {
            step_fb_kernel<<<136, 256>>>(t, W_pred, b_pred, W_act, b_act, out);
            enc_fb_kernel<<<4, 256>>>(t, W_enc, b_enc, out);
        }
        step_fb_kernel<<<136, 256>>>(NT, W_pred, b_pred, W_act, b_act, out);
    }
}

// round 13
// speedup vs baseline: 1.1503x; 1.1503x over previous
#include <cuda_runtime.h>
#include <cuda_fp16.h>
#include <math.h>

// Problem dims
#define NB 64      // batch
#define NT 512     // timesteps
#define ND 256     // input dim
#define NH 1024    // hidden
#define NL 256     // latent
#define NO 256     // output
#define NG 4096    // 4*NH gates
#define KR 1280    // NL + NH
#define BTO (NB*NT*NO)
#define NCTAS 144

// f16 SMEM layout (units = __half)
#define SWG_STRIDE 1288                    // gate weights: 32 x (1280+8)
#define SWE_STRIDE 1032                    // enc weights: 16 x (1024+8)
#define SWH_STRIDE 264                     // head weights: 32 x (256+8)
#define SA_STRIDE 264                      // A tiles: 64 x (256+8)
#define GATE_SA0 (32*SWG_STRIDE)           // 41216
#define GATE_SA1 (GATE_SA0 + 64*SA_STRIDE)
#define GATE_HALFS (GATE_SA1 + 64*SA_STRIDE)   // 75008
#define EH_HEAD_OFF (16*SWE_STRIDE)
#define EH_SA0 (EH_HEAD_OFF + 32*SWH_STRIDE)
#define EH_SA1 (EH_SA0 + 64*SA_STRIDE)
#define SMEM_BYTES (GATE_HALFS*2)          // 150016

// ---------------- device globals ---------------------------------------------
__device__ __align__(16) float g_Xp[NT * NB * NG];  // x-proj + biases [t][b][j]
__device__ __align__(16) float g_Wg[NG * KR];       // fallback packed gate weights
__device__ __align__(16) __half g_h[2][NB * NH];    // h state, double-buffered (parity t&1)
__device__ __align__(16) __half g_s[2][NB * NL];    // s state, double-buffered (parity t&1)
__device__ __align__(16) float g_hs[2][NB * KR];    // fallback state
__device__ __align__(16) float g_c[NB * NH];
__device__ unsigned g_hcnt;                         // gates: +1 after writing h(t+1)
__device__ unsigned g_scnt;                         // enc:   +1 after init-zero / writing s(t)

// ---------------- helpers ----------------------------------------------------
__device__ __forceinline__ float to_tf32(float x) {
    unsigned u;
    asm("cvt.rna.tf32.f32 %0, %1;" : "=r"(u) : "f"(x));
    return __uint_as_float(u);
}
__device__ __forceinline__ float sigmoidf_(float x) { return 1.0f / (1.0f + expf(-x)); }

__device__ __forceinline__ unsigned smem_u32(const void* p) {
    return (unsigned)__cvta_generic_to_shared(p);
}
__device__ __forceinline__ void ldm_x4(unsigned a[4], unsigned addr) {
    asm volatile("ldmatrix.sync.aligned.m8n8.x4.shared.b16 {%0,%1,%2,%3}, [%4];"
                 : "=r"(a[0]), "=r"(a[1]), "=r"(a[2]), "=r"(a[3]) : "r"(addr));
}
__device__ __forceinline__ void ldm_x2(unsigned b[2], unsigned addr) {
    asm volatile("ldmatrix.sync.aligned.m8n8.x2.shared.b16 {%0,%1}, [%2];"
                 : "=r"(b[0]), "=r"(b[1]) : "r"(addr));
}
__device__ __forceinline__ void mma16(float c[4], const unsigned a[4], const unsigned b[2]) {
    asm volatile(
        "mma.sync.aligned.m16n8k16.row.col.f32.f16.f16.f32 "
        "{%0,%1,%2,%3}, {%4,%5,%6,%7}, {%8,%9}, {%0,%1,%2,%3};"
        : "+f"(c[0]), "+f"(c[1]), "+f"(c[2]), "+f"(c[3])
        : "r"(a[0]), "r"(a[1]), "r"(a[2]), "r"(a[3]), "r"(b[0]), "r"(b[1]));
}
// fp32 tf32 mma (xproj + fallback)
__device__ __forceinline__ void mma8(float c[4], const unsigned a[4],
                                     unsigned b0, unsigned b1) {
    asm volatile(
        "mma.sync.aligned.m16n8k8.row.col.f32.tf32.tf32.f32 "
        "{%0,%1,%2,%3}, {%4,%5,%6,%7}, {%8,%9}, {%0,%1,%2,%3};\n"
        : "+f"(c[0]), "+f"(c[1]), "+f"(c[2]), "+f"(c[3])
        : "r"(a[0]), "r"(a[1]), "r"(a[2]), "r"(a[3]), "r"(b0), "r"(b1));
}

// ldmatrix address helpers (strides in __half units; layouts row-major)
__device__ __forceinline__ unsigned a_addr(const __half* sA, int m_base, int kof, int lane) {
    int grp = lane >> 3, rin = lane & 7;
    return smem_u32(sA + (m_base + (grp & 1) * 8 + rin) * SA_STRIDE + kof + (grp >> 1) * 8);
}
__device__ __forceinline__ unsigned b_addr(const __half* sW, int stride, int j0, int kof, int lane) {
    int lm = lane & 15;
    return smem_u32(sW + (j0 + (lm & 7)) * stride + kof + ((lm >> 3) & 1) * 8);
}

// stage a 64 x 256 f16 chunk: global (row stride lds) -> regs -> smem (stride 264)
__device__ __forceinline__ void lda256(uint4 rv[8], const __half* gsrc, int lds, int kc, int tid) {
    int row = tid >> 2, q = tid & 3;
    const uint4* s = reinterpret_cast<const uint4*>(gsrc + (size_t)row * lds + kc + q * 64);
#pragma unroll
    for (int i = 0; i < 8; i++) rv[i] = s[i];
}
__device__ __forceinline__ void sta256(const uint4 rv[8], __half* sA, int tid) {
    int row = tid >> 2, q = tid & 3;
    uint4* d = reinterpret_cast<uint4*>(sA + row * SA_STRIDE + q * 64);
#pragma unroll
    for (int i = 0; i < 8; i++) d[i] = rv[i];
}

// fp32 staging (xproj + fallback)
__device__ __forceinline__ void stage_A_fb(float* sA, const float* A0, int strideA,
                                           int kc, int tid) {
    int rbase = tid >> 4, c4 = (tid & 15) * 4;
#pragma unroll
    for (int i = 0; i < 4; i++) {
        const float4 v = *reinterpret_cast<const float4*>(A0 + (size_t)(rbase + i * 16) * strideA + kc + c4);
        float* d = sA + (rbase + i * 16) * 68 + c4;
        d[0] = to_tf32(v.x); d[1] = to_tf32(v.y);
        d[2] = to_tf32(v.z); d[3] = to_tf32(v.w);
    }
}
__device__ __forceinline__ void load_afrag_fb(unsigned a[4], const float* sA,
                                              int rowbase, int r, int cc, int k8) {
    const float* s0 = sA + (rowbase + r) * 68 + k8 * 8;
    a[0] = __float_as_uint(s0[cc]);
    a[1] = __float_as_uint(s0[8 * 68 + cc]);
    a[2] = __float_as_uint(s0[cc + 4]);
    a[3] = __float_as_uint(s0[8 * 68 + cc + 4]);
}

// counter wait / signal (single co-resident wave), WATCHDOG-protected:
// any sync failure escapes after ~100 ms -> wrong numerics, never a hang.
__device__ __forceinline__ void wait_cnt(unsigned* cnt, unsigned target) {
    __syncthreads();
    if (threadIdx.x == 0) {
        long long start = clock64();
        while (*(volatile unsigned*)cnt < target) {
            if (clock64() - start > 200000000LL) break;   // watchdog
        }
        __threadfence();
    }
    __syncthreads();
}
__device__ __forceinline__ void signal_cnt(unsigned* cnt) {
    __syncthreads();                       // all CTA writes done
    if (threadIdx.x == 0) {
        __threadfence();                   // make them globally visible
        atomicAdd(cnt, 1u);
    }
}

__global__ void init_kernel() { g_hcnt = 0; g_scnt = 0; }

// ---------------- xproj (unchanged, proven) ----------------------------------
__global__ void __launch_bounds__(256) xproj_kernel(const float* __restrict__ x,
                                                    const float* __restrict__ W_ih,
                                                    const float* __restrict__ b_ih,
                                                    const float* __restrict__ b_hh) {
    __shared__ float smem[64 * 68];
    int t = blockIdx.x;
    int n0 = blockIdx.y * 64;
    int tid = threadIdx.x;
    int lane = tid & 31, w = tid >> 5;
    int wm = w & 1, wn = w >> 1, r = lane >> 2, cc = lane & 3;
    float C[2][2][4] = {};
    const float* A0 = x + t * ND;
    for (int kc = 0; kc < ND; kc += 64) {
        stage_A_fb(smem, A0, NT * ND, kc, tid);
        __syncthreads();
#pragma unroll
        for (int k8 = 0; k8 < 8; k8++) {
            unsigned a0[4], a1[4];
            load_afrag_fb(a0, smem, wm * 32, r, cc, k8);
            load_afrag_fb(a1, smem, wm * 32 + 16, r, cc, k8);
#pragma unroll
            for (int nt = 0; nt < 2; nt++) {
                int j = n0 + wn * 16 + nt * 8 + r;
                const float* bp = W_ih + (size_t)j * (ND + NL) + kc + k8 * 8 + cc;
                unsigned b0 = __float_as_uint(to_tf32(bp[0]));
                unsigned b1 = __float_as_uint(to_tf32(bp[4]));
                mma8(C[0][nt], a0, b0, b1);
                mma8(C[1][nt], a1, b0, b1);
            }
        }
        __syncthreads();
    }
#pragma unroll
    for (int mt = 0; mt < 2; mt++)
#pragma unroll
        for (int nt = 0; nt < 2; nt++) {
            int col = n0 + wn * 16 + nt * 8 + 2 * cc;
            int row0 = wm * 32 + mt * 16 + r;
            float bs0 = b_ih[col] + b_hh[col];
            float bs1 = b_ih[col + 1] + b_hh[col + 1];
            size_t base0 = ((size_t)t * NB + row0) * NG;
            size_t base1 = ((size_t)t * NB + row0 + 8) * NG;
            g_Xp[base0 + col]     = C[mt][nt][0] + bs0;
            g_Xp[base0 + col + 1] = C[mt][nt][1] + bs1;
            g_Xp[base1 + col]     = C[mt][nt][2] + bs0;
            g_Xp[base1 + col + 1] = C[mt][nt][3] + bs1;
        }
}

// ---------------- persistent kernel (fp16 + ldmatrix, split-role sync) -------
// Buffering: h(t+1) lives in g_h[t&1]; s(t) lives in g_s[t&1]; s(-1)=g_s[1]=0.
// g_scnt: 16 at init-zero done; +16 per enc step -> s(t) ready at 16*(t+2).
// g_hcnt: +128 per gate step  -> h(t+1) ready at 128*(t+1).
extern __shared__ __half dsmh[];

__global__ void __launch_bounds__(256, 1)
persist_kernel(const float* __restrict__ W_ih, const float* __restrict__ W_hh,
               const float* __restrict__ W_enc, const float* __restrict__ b_enc,
               const float* __restrict__ W_pred, const float* __restrict__ b_pred,
               const float* __restrict__ W_act, const float* __restrict__ b_act,
               float* __restrict__ out) {
    int bx = blockIdx.x;
    int tid = threadIdx.x;
    int lane = tid & 31, w = tid >> 5;
    int r = lane >> 2, cc = lane & 3;

    if (bx < 128) {
        // ================= gate CTA: 8 units x 4 gates =================
        __half* sW = dsmh;
        __half* sA0 = dsmh + GATE_SA0;
        __half* sA1 = dsmh + GATE_SA1;
        int wm = w & 1, wn = w >> 1;     // wm: m-half, wn: gate
        int u0 = bx * 8;

        for (int idx = tid; idx < 32 * KR; idx += 256) {
            int rl = idx / KR, k = idx - rl * KR;
            int g = rl >> 3, up = rl & 7;
            int j = g * NH + u0 + up;
            float v = (k < NL) ? W_ih[(size_t)j * (ND + NL) + ND + k]
                               : W_hh[(size_t)j * NH + k - NL];
            sW[rl * SWG_STRIDE + k] = __float2half(v);
        }
        for (int idx = tid; idx < 512; idx += 256) {
            int b = idx >> 3, up = idx & 7;
            g_c[b * NH + u0 + up] = 0.0f;
        }

        float C[2][4] = {};
        float xp[2][4];
#pragma unroll
        for (int q = 0; q < 2; q++) {            // prefetch Xp for t=0
            int idx = tid + q * 256;
            int b = idx >> 3, up = idx & 7;
            size_t base = (size_t)b * NG + u0 + up;
#pragma unroll
            for (int g = 0; g < 4; g++) xp[q][g] = __ldg(&g_Xp[base + g * NH]);
        }

        for (int t = 0; t < NT; t++) {
            // s(t-1) ready?  (init-zero counts as the first 16; usually no wait)
            wait_cnt(&g_scnt, 16u * (unsigned)(t + 1));

            // ---------- phase A: Gs(K=256) + cell ----------
            const __half* sbuf = g_s[(t + 1) & 1];   // s(t-1)
            __half* hbuf = g_h[t & 1];               // h(t+1) destination
            {
                uint4 rv[8];
                lda256(rv, sbuf, NL, 0, tid);
                sta256(rv, sA0, tid);
                __syncthreads();
#pragma unroll 4
                for (int kk = 0; kk < 16; kk++) {
                    unsigned a0[4], a1[4], b[2];
                    ldm_x4(a0, a_addr(sA0, wm * 32, kk * 16, lane));
                    ldm_x4(a1, a_addr(sA0, wm * 32 + 16, kk * 16, lane));
                    ldm_x2(b, b_addr(sW, SWG_STRIDE, wn * 8, kk * 16, lane));
                    mma16(C[0], a0, b);
                    mma16(C[1], a1, b);
                }
                // scatter gates into sG (= sA1 region, as f32)
                float* sG = reinterpret_cast<float*>(sA1);
#pragma unroll
                for (int mt = 0; mt < 2; mt++) {
                    int brow = wm * 32 + mt * 16 + r;
                    sG[(wn * 64 + brow) * 9 + 2 * cc]         = C[mt][0];
                    sG[(wn * 64 + brow) * 9 + 2 * cc + 1]     = C[mt][1];
                    sG[(wn * 64 + brow + 8) * 9 + 2 * cc]     = C[mt][2];
                    sG[(wn * 64 + brow + 8) * 9 + 2 * cc + 1] = C[mt][3];
                }
                __syncthreads();
#pragma unroll
                for (int q = 0; q < 2; q++) {
                    int idx = tid + q * 256;
                    int b = idx >> 3, up = idx & 7, u = u0 + up;
                    float gi = sG[(0 * 64 + b) * 9 + up] + xp[q][0];
                    float gf = sG[(1 * 64 + b) * 9 + up] + xp[q][1];
                    float gg = sG[(2 * 64 + b) * 9 + up] + xp[q][2];
                    float go = sG[(3 * 64 + b) * 9 + up] + xp[q][3];
                    float ii = sigmoidf_(gi), ff = sigmoidf_(gf);
                    float gt = tanhf(gg), oo = sigmoidf_(go);
                    float cn = ff * g_c[b * NH + u] + ii * gt;
                    g_c[b * NH + u] = cn;
                    hbuf[b * NH + u] = __float2half(oo * tanhf(cn));
                }
                C[0][0] = C[0][1] = C[0][2] = C[0][3] = 0.0f;
                C[1][0] = C[1][1] = C[1][2] = C[1][3] = 0.0f;
            }
            signal_cnt(&g_hcnt);                       // h(t+1) published

            // ---------- phase B: Gh(K=1024) for step t+1 ----------
            if (t + 1 < NT) {
                wait_cnt(&g_hcnt, 128u * (unsigned)(t + 1));   // full h(t+1)
#pragma unroll
                for (int q = 0; q < 2; q++) {     // prefetch Xp for t+1
                    int idx = tid + q * 256;
                    int b = idx >> 3, up = idx & 7;
                    size_t base = ((size_t)(t + 1) * NB + b) * NG + u0 + up;
#pragma unroll
                    for (int g = 0; g < 4; g++) xp[q][g] = __ldg(&g_Xp[base + g * NH]);
                }
                uint4 rv[8];
                lda256(rv, hbuf, NH, 0, tid);
                sta256(rv, sA0, tid);
                lda256(rv, hbuf, NH, 256, tid);
                __syncthreads();
#pragma unroll 1
                for (int c = 0; c < 4; c++) {
                    const __half* cur = (c & 1) ? sA1 : sA0;
                    int wk = NL + c * 256;
#pragma unroll 4
                    for (int kk = 0; kk < 16; kk++) {
                        unsigned a0[4], a1[4], b[2];
                        ldm_x4(a0, a_addr(cur, wm * 32, kk * 16, lane));
                        ldm_x4(a1, a_addr(cur, wm * 32 + 16, kk * 16, lane));
                        ldm_x2(b, b_addr(sW, SWG_STRIDE, wn * 8, wk + kk * 16, lane));
                        mma16(C[0], a0, b);
                        mma16(C[1], a1, b);
                    }
                    if (c + 1 < 4) {
                        sta256(rv, (c & 1) ? sA0 : sA1, tid);
                        if (c + 2 < 4) lda256(rv, hbuf, NH, (c + 2) * 256, tid);
                    }
                    __syncthreads();
                }
            }
        }
    } else {
        // ================= enc + head CTA =================
        int e = bx - 128;
        __half* sWe = dsmh;
        __half* sWh = dsmh + EH_HEAD_OFF;
        __half* sA0 = dsmh + EH_SA0;
        __half* sA1 = dsmh + EH_SA1;

        for (int idx = tid; idx < 16 * NH; idx += 256) {
            int rl = idx >> 10, k = idx & 1023;
            sWe[rl * SWE_STRIDE + k] = __float2half(W_enc[(size_t)(e * 16 + rl) * NH + k]);
        }
        const float* Wh = (e < 8) ? W_act : W_pred;
        int hr0 = (e < 8) ? e * 32 : (e - 8) * 32;
        for (int idx = tid; idx < 32 * NL; idx += 256) {
            int rl = idx >> 8, k = idx & 255;
            sWh[rl * SWH_STRIDE + k] = __float2half(Wh[(size_t)(hr0 + rl) * NL + k]);
        }
        for (int idx = tid; idx < 2048; idx += 256) {       // zero BOTH s buffers
            int buf = idx >> 10, rem = idx & 1023;
            int b = rem >> 4, q = rem & 15;
            g_s[buf][b * NL + e * 16 + q] = __float2half(0.0f);
        }
        signal_cnt(&g_scnt);                    // init zero published (counts 16)

        for (int t = 0; t <= NT; t++) {
            // ---------- phase A: heads for step t-1 (K=256 from s(t-1)) ------
            if (t >= 1) {
                wait_cnt(&g_scnt, 16u * (unsigned)(t + 1));   // all of s(t-1)
                int wm = w & 1, wn = w >> 1;
                float C[2][4] = {};
                uint4 rv[8];
                lda256(rv, g_s[(t + 1) & 1], NL, 0, tid);     // s(t-1)
                sta256(rv, sA0, tid);
                __syncthreads();
#pragma unroll 4
                for (int kk = 0; kk < 16; kk++) {
                    unsigned a0[4], a1[4], b[2];
                    ldm_x4(a0, a_addr(sA0, wm * 32, kk * 16, lane));
                    ldm_x4(a1, a_addr(sA0, wm * 32 + 16, kk * 16, lane));
                    ldm_x2(b, b_addr(sWh, SWH_STRIDE, wn * 8, kk * 16, lane));
                    mma16(C[0], a0, b);
                    mma16(C[1], a1, b);
                }
                bool isAct = (e < 8);
                const float* bias = isAct ? b_act : b_pred;
                size_t obase = isAct ? (size_t)0 : (size_t)2 * BTO;
#pragma unroll
                for (int mt = 0; mt < 2; mt++) {
                    int row0 = wm * 32 + mt * 16 + r;
                    int coll = hr0 + wn * 8 + 2 * cc;
#pragma unroll
                    for (int el = 0; el < 4; el++) {
                        int rr = row0 + (el >> 1) * 8;
                        int col = coll + (el & 1);
                        float v = C[mt][el] + __ldg(&bias[col]);
                        if (!isAct) v = tanhf(v);
                        out[obase + ((size_t)rr * NT + (t - 1)) * NO + col] = v;
                    }
                }
            }
            if (t == NT) break;

            // ---------- phase B: enc 16 cols (K=1024 from h(t+1)) ------------
            {
                wait_cnt(&g_hcnt, 128u * (unsigned)(t + 1));  // full h(t+1)
                const __half* hbuf = g_h[t & 1];
                int wm4 = w & 3, wn2 = w >> 2;
                float C[4] = {};
                uint4 rv[8];
                lda256(rv, hbuf, NH, 0, tid);
                sta256(rv, sA0, tid);
                lda256(rv, hbuf, NH, 256, tid);
                __syncthreads();
#pragma unroll 1
                for (int c = 0; c < 4; c++) {
                    const __half* cur = (c & 1) ? sA1 : sA0;
#pragma unroll 4
                    for (int kk = 0; kk < 16; kk++) {
                        unsigned a0[4], b[2];
                        ldm_x4(a0, a_addr(cur, wm4 * 16, kk * 16, lane));
                        ldm_x2(b, b_addr(sWe, SWE_STRIDE, wn2 * 8, c * 256 + kk * 16, lane));
                        mma16(C, a0, b);
                    }
                    if (c + 1 < 4) {
                        sta256(rv, (c & 1) ? sA0 : sA1, tid);
                        if (c + 2 < 4) lda256(rv, hbuf, NH, (c + 2) * 256, tid);
                    }
                    __syncthreads();
                }
                int row0 = wm4 * 16 + r;
                int coll = e * 16 + wn2 * 8 + 2 * cc;
#pragma unroll
                for (int el = 0; el < 4; el++) {
                    int rr = row0 + (el >> 1) * 8;
                    int col = coll + (el & 1);
                    float v = tanhf(C[el] + __ldg(&b_enc[col]));
                    g_s[t & 1][rr * NL + col] = __float2half(v);
                    out[(size_t)BTO + ((size_t)rr * NT + t) * NL + col] = v;
                }
                signal_cnt(&g_scnt);            // s(t) published
            }
        }
    }
}

// ================= fallback path (proven in R6/R8; terminates always) ========
__global__ void __launch_bounds__(256) prep_fb_kernel(const float* __restrict__ W_ih,
                                                      const float* __restrict__ W_hh) {
    const int N0 = NG * KR;
    const int N1 = 2 * NB * KR;
    const int N2 = NB * NH;
    const int total = N0 + N1 + N2;
    for (int i = blockIdx.x * blockDim.x + threadIdx.x; i < total;
         i += gridDim.x * blockDim.x) {
        int k = i;
        if (k < N0) {
            int j = k / KR, q = k - j * KR;
            float v = (q < NL) ? W_ih[(size_t)j * (ND + NL) + ND + q]
                               : W_hh[(size_t)j * NH + (q - NL)];
            g_Wg[k] = to_tf32(v);
        } else if ((k -= N0) < N1) {
            (&g_hs[0][0])[k] = 0.0f;
        } else {
            k -= N1;
            g_c[k] = 0.0f;
        }
    }
}

__device__ __forceinline__ void gemm_fb(float C[2][2][4], const float* A0, int strideA,
                                        const float* Bw, int ldb, int jbase, int K,
                                        float* sA) {
    int tid = threadIdx.x;
    int lane = tid & 31, w = tid >> 5;
    int wm = w & 1, wn = w >> 1, r = lane >> 2, cc = lane & 3;
    for (int kc = 0; kc < K; kc += 64) {
        stage_A_fb(sA, A0, strideA, kc, tid);
        __syncthreads();
#pragma unroll
        for (int k8 = 0; k8 < 8; k8++) {
            unsigned a0[4], a1[4];
            load_afrag_fb(a0, sA, wm * 32, r, cc, k8);
            load_afrag_fb(a1, sA, wm * 32 + 16, r, cc, k8);
#pragma unroll
            for (int nt = 0; nt < 2; nt++) {
                int j = jbase + wn * 16 + nt * 8 + r;
                const float* bp = Bw + (size_t)j * ldb + kc + k8 * 8 + cc;
                unsigned b0 = __float_as_uint(bp[0]);
                unsigned b1 = __float_as_uint(bp[4]);
                mma8(C[0][nt], a0, b0, b1);
                mma8(C[1][nt], a1, b0, b1);
            }
        }
        __syncthreads();
    }
}

__global__ void __launch_bounds__(256) step_fb_kernel(int t,
                                                      const float* __restrict__ W_pred,
                                                      const float* __restrict__ b_pred,
                                                      const float* __restrict__ W_act,
                                                      const float* __restrict__ b_act,
                                                      float* __restrict__ out) {
    __shared__ float smem[64 * 68];
    const float* hs_cur = g_hs[t & 1];
    float* hs_nxt = g_hs[(t + 1) & 1];
    int bx = blockIdx.x;
    int tid = threadIdx.x;
    int lane = tid & 31, w = tid >> 5;
    int wm = w & 1, wn = w >> 1, r = lane >> 2, cc = lane & 3;

    if (bx < 128) {
        if (t >= NT) return;
        int u0 = bx * 8;
        float C[2][4] = {};
        for (int kc = 0; kc < KR; kc += 64) {
            stage_A_fb(smem, hs_cur, KR, kc, tid);
            __syncthreads();
#pragma unroll
            for (int k8 = 0; k8 < 8; k8++) {
                unsigned a0[4], a1[4];
                load_afrag_fb(a0, smem, wm * 32, r, cc, k8);
                load_afrag_fb(a1, smem, wm * 32 + 16, r, cc, k8);
                int j = wn * NH + u0 + r;
                const float* bp = g_Wg + (size_t)j * KR + kc + k8 * 8 + cc;
                unsigned b0 = __float_as_uint(bp[0]);
                unsigned b1 = __float_as_uint(bp[4]);
                mma8(C[0], a0, b0, b1);
                mma8(C[1], a1, b0, b1);
            }
            __syncthreads();
        }
        float* sG = smem;
#pragma unroll
        for (int mt = 0; mt < 2; mt++) {
            int b0r = wm * 32 + mt * 16 + r;
            sG[(wn * 64 + b0r) * 9 + 2 * cc]         = C[mt][0];
            sG[(wn * 64 + b0r) * 9 + 2 * cc + 1]     = C[mt][1];
            sG[(wn * 64 + b0r + 8) * 9 + 2 * cc]     = C[mt][2];
            sG[(wn * 64 + b0r + 8) * 9 + 2 * cc + 1] = C[mt][3];
        }
        __syncthreads();
        for (int idx = tid; idx < 512; idx += 256) {
            int b = idx >> 3, up = idx & 7, u = u0 + up;
            size_t xb = ((size_t)t * NB + b) * NG;
            float gi = sG[(0 * 64 + b) * 9 + up] + g_Xp[xb + u];
            float gf = sG[(1 * 64 + b) * 9 + up] + g_Xp[xb + NH + u];
            float gg = sG[(2 * 64 + b) * 9 + up] + g_Xp[xb + 2 * NH + u];
            float go = sG[(3 * 64 + b) * 9 + up] + g_Xp[xb + 3 * NH + u];
            float ii = sigmoidf_(gi), ff = sigmoidf_(gf);
            float gt = tanhf(gg), oo = sigmoidf_(go);
            float cn = ff * g_c[b * NH + u] + ii * gt;
            g_c[b * NH + u] = cn;
            hs_nxt[b * KR + NL + u] = oo * tanhf(cn);
        }
    } else {
        if (t == 0) return;
        int ab = bx - 128;
        bool isAct = ab < 4;
        int n0 = (ab & 3) * 64;
        float C[2][2][4] = {};
        gemm_fb(C, hs_cur, KR, isAct ? W_act : W_pred, NL, n0, NL, smem);
        const float* bias = isAct ? b_act : b_pred;
        size_t obase = isAct ? (size_t)0 : (size_t)2 * BTO;
#pragma unroll
        for (int mt = 0; mt < 2; mt++)
#pragma unroll
            for (int nt = 0; nt < 2; nt++) {
                int col = n0 + wn * 16 + nt * 8 + 2 * cc;
                int row0 = wm * 32 + mt * 16 + r;
#pragma unroll
                for (int el = 0; el < 4; el++) {
                    int rr = row0 + (el >> 1) * 8;
                    int jj = col + (el & 1);
                    float v = C[mt][nt][el] + bias[jj];
                    if (!isAct) v = tanhf(v);
                    out[obase + ((size_t)rr * NT + (t - 1)) * NO + jj] = v;
                }
            }
    }
}

__global__ void __launch_bounds__(256) enc_fb_kernel(int t,
                                                     const float* __restrict__ W_enc,
                                                     const float* __restrict__ b_enc,
                                                     float* __restrict__ out) {
    __shared__ float smem[64 * 68];
    float* hs_nxt = g_hs[(t + 1) & 1];
    int n0 = blockIdx.x * 64;
    float C[2][2][4] = {};
    gemm_fb(C, hs_nxt + NL, KR, W_enc, NH, n0, NH, smem);

    int lane = threadIdx.x & 31, w = threadIdx.x >> 5;
    int wm = w & 1, wn = w >> 1, r = lane >> 2, cc = lane & 3;
#pragma unroll
    for (int mt = 0; mt < 2; mt++)
#pragma unroll
        for (int nt = 0; nt < 2; nt++) {
            int col = n0 + wn * 16 + nt * 8 + 2 * cc;
            int row0 = wm * 32 + mt * 16 + r;
#pragma unroll
            for (int el = 0; el < 4; el++) {
                int rr = row0 + (el >> 1) * 8;
                int jj = col + (el & 1);
                float v = tanhf(C[mt][nt][el] + b_enc[jj]);
                out[(size_t)BTO + ((size_t)rr * NT + t) * NL + jj] = v;
                hs_nxt[rr * KR + jj] = v;
            }
        }
}

// ---------------- host driver ------------------------------------------------
extern "C" void kernel_launch(void* const* d_in, const int* in_sizes, int n_in,
                              void* d_out, int out_size) {
    const float* x      = (const float*)d_in[0];
    const float* W_ih   = (const float*)d_in[1];
    const float* W_hh   = (const float*)d_in[2];
    const float* b_ih   = (const float*)d_in[3];
    const float* b_hh   = (const float*)d_in[4];
    const float* W_enc  = (const float*)d_in[5];
    const float* b_enc  = (const float*)d_in[6];
    const float* W_pred = (const float*)d_in[7];
    const float* b_pred = (const float*)d_in[8];
    const float* W_act  = (const float*)d_in[9];
    const float* b_act  = (const float*)d_in[10];
    float* out = (float*)d_out;

    int dev = 0, nsm = 0;
    cudaGetDevice(&dev);
    cudaDeviceGetAttribute(&nsm, cudaDevAttrMultiProcessorCount, dev);
    bool persistent_ok = (nsm >= NCTAS);
    if (persistent_ok) {
        cudaError_t e = cudaFuncSetAttribute(
            persist_kernel, cudaFuncAttributeMaxDynamicSharedMemorySize, SMEM_BYTES);
        if (e != cudaSuccess) { (void)cudaGetLastError(); persistent_ok = false; }
    }

    xproj_kernel<<<dim3(NT, NG / 64), 256>>>(x, W_ih, b_ih, b_hh);

    if (persistent_ok) {
        init_kernel<<<1, 1>>>();
        persist_kernel<<<NCTAS, 256, SMEM_BYTES>>>(W_ih, W_hh, W_enc, b_enc,
                                                   W_pred, b_pred, W_act, b_act, out);
    } else {
        prep_fb_kernel<<<1024, 256>>>(W_ih, W_hh);
        for (int t = 0; t < NT; t++) {
            step_fb_kernel<<<136, 256>>>(t, W_pred, b_pred, W_act, b_act, out);
            enc_fb_kernel<<<4, 256>>>(t, W_enc, b_enc, out);
        }
        step_fb_kernel<<<136, 256>>>(NT, W_pred, b_pred, W_act, b_act, out);
    }
}